// round 2
// baseline (speedup 1.0000x reference)
#include <cuda_runtime.h>

// MovingAvgNorm: x (B=32, T=16384, D=80) fp32, window K=100 over T with
// reflect padding (50 left, 49 right), unbiased std.
//
// R2 design: float4-vectorized over D (20 vec-lanes/row). One thread owns
// (b, t-subchunk, dvec) and slides an O(1) running-sum window over TSUB=128
// outputs. 81,920 threads total for latency hiding. Interior chunks take a
// reflection-free fast path. Output stored with .cs (no reuse).

#define MAN_B      32
#define MAN_T      16384
#define MAN_DV     20        // 80 floats = 20 float4
#define MAN_K      100
#define MAN_H      50        // K/2
#define MAN_TSUB   128
#define MAN_NCHUNK (MAN_T / MAN_TSUB)   // 128

__device__ __forceinline__ int refl(int o) {
    if (o < 0) return -o;
    if (o >= MAN_T) return 2 * MAN_T - 2 - o;
    return o;
}

__device__ __forceinline__ void acc(float4& s1, float4& s2, float4 v) {
    s1.x += v.x; s1.y += v.y; s1.z += v.z; s1.w += v.w;
    s2.x = fmaf(v.x, v.x, s2.x);
    s2.y = fmaf(v.y, v.y, s2.y);
    s2.z = fmaf(v.z, v.z, s2.z);
    s2.w = fmaf(v.w, v.w, s2.w);
}

__device__ __forceinline__ float norm1(float xc, float s1, float s2,
                                       float inv_k, float inv_k1) {
    float m   = s1 * inv_k;
    float var = (s2 - s1 * m) * inv_k1;
    float rsd = rsqrtf(fmaxf(var, 1e-24f));
    return (xc - m) * rsd;
}

__device__ __forceinline__ void step(float4& s1, float4& s2,
                                     float4 va, float4 vr) {
    s1.x += va.x - vr.x;  s1.y += va.y - vr.y;
    s1.z += va.z - vr.z;  s1.w += va.w - vr.w;
    s2.x = fmaf(va.x, va.x, fmaf(-vr.x, vr.x, s2.x));
    s2.y = fmaf(va.y, va.y, fmaf(-vr.y, vr.y, s2.y));
    s2.z = fmaf(va.z, va.z, fmaf(-vr.z, vr.z, s2.z));
    s2.w = fmaf(va.w, va.w, fmaf(-vr.w, vr.w, s2.w));
}

__global__ __launch_bounds__(256) void moving_avg_norm_v2(
    const float4* __restrict__ x, float4* __restrict__ out)
{
    const int tid  = blockIdx.x * blockDim.x + threadIdx.x;
    const int dv   = tid % MAN_DV;
    const int rest = tid / MAN_DV;
    const int c    = rest % MAN_NCHUNK;
    const int b    = rest / MAN_NCHUNK;
    const int t0   = c * MAN_TSUB;

    const float4* __restrict__ xb = x   + (size_t)b * MAN_T * MAN_DV + dv;
    float4* __restrict__       ob = out + (size_t)b * MAN_T * MAN_DV + dv;

    const float inv_k  = 1.0f / MAN_K;
    const float inv_k1 = 1.0f / (MAN_K - 1);

    float4 s1 = make_float4(0.f, 0.f, 0.f, 0.f);
    float4 s2 = make_float4(0.f, 0.f, 0.f, 0.f);

    const bool edge = (t0 < MAN_H) || (t0 + MAN_TSUB + MAN_H > MAN_T);

    if (!edge) {
        // ---- interior fast path: no reflection anywhere ----
        #pragma unroll 5
        for (int o = t0 - MAN_H; o < t0 + MAN_H; ++o) {
            float4 v = __ldg(xb + (size_t)o * MAN_DV);
            acc(s1, s2, v);
        }
        #pragma unroll 4
        for (int t = t0; t < t0 + MAN_TSUB; ++t) {
            float4 xc = __ldg(xb + (size_t)t * MAN_DV);
            float4 va = __ldg(xb + (size_t)(t + MAN_H) * MAN_DV);
            float4 vr = __ldg(xb + (size_t)(t - MAN_H) * MAN_DV);
            float4 r;
            r.x = norm1(xc.x, s1.x, s2.x, inv_k, inv_k1);
            r.y = norm1(xc.y, s1.y, s2.y, inv_k, inv_k1);
            r.z = norm1(xc.z, s1.z, s2.z, inv_k, inv_k1);
            r.w = norm1(xc.w, s1.w, s2.w, inv_k, inv_k1);
            __stcs(ob + (size_t)t * MAN_DV, r);
            step(s1, s2, va, vr);
        }
    } else {
        // ---- edge path: reflected indices ----
        #pragma unroll 5
        for (int o = t0 - MAN_H; o < t0 + MAN_H; ++o) {
            float4 v = __ldg(xb + (size_t)refl(o) * MAN_DV);
            acc(s1, s2, v);
        }
        #pragma unroll 4
        for (int t = t0; t < t0 + MAN_TSUB; ++t) {
            float4 xc = __ldg(xb + (size_t)t * MAN_DV);
            int oa = t + MAN_H;
            oa = (oa >= MAN_T) ? (2 * MAN_T - 2 - oa) : oa;
            int orm = t - MAN_H;
            orm = (orm < 0) ? -orm : orm;
            float4 va = __ldg(xb + (size_t)oa  * MAN_DV);
            float4 vr = __ldg(xb + (size_t)orm * MAN_DV);
            float4 r;
            r.x = norm1(xc.x, s1.x, s2.x, inv_k, inv_k1);
            r.y = norm1(xc.y, s1.y, s2.y, inv_k, inv_k1);
            r.z = norm1(xc.z, s1.z, s2.z, inv_k, inv_k1);
            r.w = norm1(xc.w, s1.w, s2.w, inv_k, inv_k1);
            __stcs(ob + (size_t)t * MAN_DV, r);
            step(s1, s2, va, vr);
        }
    }
}

extern "C" void kernel_launch(void* const* d_in, const int* in_sizes, int n_in,
                              void* d_out, int out_size)
{
    const float4* x = (const float4*)d_in[0];
    float4* out = (float4*)d_out;
    (void)in_sizes; (void)n_in; (void)out_size;

    const int total = MAN_B * MAN_NCHUNK * MAN_DV;   // 81,920 threads
    const int block = 256;
    moving_avg_norm_v2<<<total / block, block>>>(x, out);
}

// round 3
// speedup vs baseline: 1.5942x; 1.5942x over previous
#include <cuda_runtime.h>

// MovingAvgNorm: x (B=32, T=16384, D=80) fp32, window K=100 over T with
// reflect padding (50 left, 49 right), unbiased std.
//
// R3: float4 over D (20 vec-lanes), O(1) sliding window per thread, but
// TSUB=32 so the grid is 1280 blocks (327,680 threads) — R2's 320-block grid
// left the chip at 23% occupancy and latency-bound. Halo re-reads from the
// shorter chunks hit L2 (input fits 126MB L2), so DRAM traffic is unchanged.

#define MAN_B      32
#define MAN_T      16384
#define MAN_DV     20        // 80 floats = 20 float4
#define MAN_K      100
#define MAN_H      50        // K/2
#define MAN_TSUB   32
#define MAN_NCHUNK (MAN_T / MAN_TSUB)   // 512

__device__ __forceinline__ int refl(int o) {
    if (o < 0) return -o;
    if (o >= MAN_T) return 2 * MAN_T - 2 - o;
    return o;
}

__device__ __forceinline__ void acc(float4& s1, float4& s2, float4 v) {
    s1.x += v.x; s1.y += v.y; s1.z += v.z; s1.w += v.w;
    s2.x = fmaf(v.x, v.x, s2.x);
    s2.y = fmaf(v.y, v.y, s2.y);
    s2.z = fmaf(v.z, v.z, s2.z);
    s2.w = fmaf(v.w, v.w, s2.w);
}

__device__ __forceinline__ float norm1(float xc, float s1, float s2,
                                       float inv_k, float inv_k1) {
    float m   = s1 * inv_k;
    float var = (s2 - s1 * m) * inv_k1;
    float rsd = rsqrtf(fmaxf(var, 1e-24f));
    return (xc - m) * rsd;
}

__device__ __forceinline__ void step(float4& s1, float4& s2,
                                     float4 va, float4 vr) {
    s1.x += va.x - vr.x;  s1.y += va.y - vr.y;
    s1.z += va.z - vr.z;  s1.w += va.w - vr.w;
    s2.x = fmaf(va.x, va.x, fmaf(-vr.x, vr.x, s2.x));
    s2.y = fmaf(va.y, va.y, fmaf(-vr.y, vr.y, s2.y));
    s2.z = fmaf(va.z, va.z, fmaf(-vr.z, vr.z, s2.z));
    s2.w = fmaf(va.w, va.w, fmaf(-vr.w, vr.w, s2.w));
}

__global__ __launch_bounds__(256, 6) void moving_avg_norm_v3(
    const float4* __restrict__ x, float4* __restrict__ out)
{
    const int tid  = blockIdx.x * blockDim.x + threadIdx.x;
    const int dv   = tid % MAN_DV;
    const int rest = tid / MAN_DV;
    const int c    = rest % MAN_NCHUNK;
    const int b    = rest / MAN_NCHUNK;
    const int t0   = c * MAN_TSUB;

    const float4* __restrict__ xb = x   + (size_t)b * MAN_T * MAN_DV + dv;
    float4* __restrict__       ob = out + (size_t)b * MAN_T * MAN_DV + dv;

    const float inv_k  = 1.0f / MAN_K;
    const float inv_k1 = 1.0f / (MAN_K - 1);

    float4 s1 = make_float4(0.f, 0.f, 0.f, 0.f);
    float4 s2 = make_float4(0.f, 0.f, 0.f, 0.f);

    const bool edge = (t0 < MAN_H) || (t0 + MAN_TSUB + MAN_H > MAN_T);

    if (!edge) {
        // ---- interior fast path: no reflection anywhere ----
        #pragma unroll 5
        for (int o = t0 - MAN_H; o < t0 + MAN_H; ++o) {
            float4 v = __ldg(xb + (size_t)o * MAN_DV);
            acc(s1, s2, v);
        }
        #pragma unroll 8
        for (int t = t0; t < t0 + MAN_TSUB; ++t) {
            float4 xc = __ldg(xb + (size_t)t * MAN_DV);
            float4 va = __ldg(xb + (size_t)(t + MAN_H) * MAN_DV);
            float4 vr = __ldg(xb + (size_t)(t - MAN_H) * MAN_DV);
            float4 r;
            r.x = norm1(xc.x, s1.x, s2.x, inv_k, inv_k1);
            r.y = norm1(xc.y, s1.y, s2.y, inv_k, inv_k1);
            r.z = norm1(xc.z, s1.z, s2.z, inv_k, inv_k1);
            r.w = norm1(xc.w, s1.w, s2.w, inv_k, inv_k1);
            __stcs(ob + (size_t)t * MAN_DV, r);
            step(s1, s2, va, vr);
        }
    } else {
        // ---- edge path: reflected indices ----
        #pragma unroll 5
        for (int o = t0 - MAN_H; o < t0 + MAN_H; ++o) {
            float4 v = __ldg(xb + (size_t)refl(o) * MAN_DV);
            acc(s1, s2, v);
        }
        #pragma unroll 4
        for (int t = t0; t < t0 + MAN_TSUB; ++t) {
            float4 xc = __ldg(xb + (size_t)t * MAN_DV);
            int oa = t + MAN_H;
            oa = (oa >= MAN_T) ? (2 * MAN_T - 2 - oa) : oa;
            int orm = t - MAN_H;
            orm = (orm < 0) ? -orm : orm;
            float4 va = __ldg(xb + (size_t)oa  * MAN_DV);
            float4 vr = __ldg(xb + (size_t)orm * MAN_DV);
            float4 r;
            r.x = norm1(xc.x, s1.x, s2.x, inv_k, inv_k1);
            r.y = norm1(xc.y, s1.y, s2.y, inv_k, inv_k1);
            r.z = norm1(xc.z, s1.z, s2.z, inv_k, inv_k1);
            r.w = norm1(xc.w, s1.w, s2.w, inv_k, inv_k1);
            __stcs(ob + (size_t)t * MAN_DV, r);
            step(s1, s2, va, vr);
        }
    }
}

extern "C" void kernel_launch(void* const* d_in, const int* in_sizes, int n_in,
                              void* d_out, int out_size)
{
    const float4* x = (const float4*)d_in[0];
    float4* out = (float4*)d_out;
    (void)in_sizes; (void)n_in; (void)out_size;

    const int total = MAN_B * MAN_NCHUNK * MAN_DV;   // 327,680 threads
    const int block = 256;
    moving_avg_norm_v3<<<total / block, block>>>(x, out);
}

// round 4
// speedup vs baseline: 1.8998x; 1.1917x over previous
#include <cuda_runtime.h>

// MovingAvgNorm: x (B=32, T=16384, D=80) fp32, window K=100 over T,
// reflect pad (50 left, 49 right), unbiased std.
//
// R4: smem-tiled. Block = (b, 128-row T-chunk). Cooperative load of the
// chunk + 100-row halo (228 rows x 320B = 72.9KB smem, reflection applied at
// load). Then 320 threads = 20 float4 d-lanes x 16 segments of 8 outputs,
// each sliding an O(1) s1/s2 window over smem. DRAM read amplification drops
// from 4.1x (R3, 32-row chunks through L2) to 1.78x.

#define MAN_B      32
#define MAN_T      16384
#define MAN_DV     20          // 80 floats = 20 float4
#define MAN_K      100
#define MAN_H      50
#define MAN_TSUB   128
#define MAN_ROWS   (MAN_TSUB + MAN_K)     // 228
#define MAN_NTH    320
#define MAN_SEG    8
#define MAN_NCHUNK (MAN_T / MAN_TSUB)     // 128
#define MAN_SMEM   (MAN_ROWS * MAN_DV * 16)   // 72960 bytes

__device__ __forceinline__ void acc(float4& s1, float4& s2, float4 v) {
    s1.x += v.x; s1.y += v.y; s1.z += v.z; s1.w += v.w;
    s2.x = fmaf(v.x, v.x, s2.x);
    s2.y = fmaf(v.y, v.y, s2.y);
    s2.z = fmaf(v.z, v.z, s2.z);
    s2.w = fmaf(v.w, v.w, s2.w);
}

__device__ __forceinline__ float norm1(float xc, float s1, float s2,
                                       float inv_k, float inv_k1) {
    float m   = s1 * inv_k;
    float var = (s2 - s1 * m) * inv_k1;
    float rsd = rsqrtf(fmaxf(var, 1e-24f));
    return (xc - m) * rsd;
}

__device__ __forceinline__ void step(float4& s1, float4& s2,
                                     float4 va, float4 vr) {
    s1.x += va.x - vr.x;  s1.y += va.y - vr.y;
    s1.z += va.z - vr.z;  s1.w += va.w - vr.w;
    s2.x = fmaf(va.x, va.x, fmaf(-vr.x, vr.x, s2.x));
    s2.y = fmaf(va.y, va.y, fmaf(-vr.y, vr.y, s2.y));
    s2.z = fmaf(va.z, va.z, fmaf(-vr.z, vr.z, s2.z));
    s2.w = fmaf(va.w, va.w, fmaf(-vr.w, vr.w, s2.w));
}

__global__ __launch_bounds__(MAN_NTH, 3) void moving_avg_norm_v4(
    const float4* __restrict__ x, float4* __restrict__ out)
{
    extern __shared__ float4 tile[];    // [MAN_ROWS * MAN_DV]

    const int b  = blockIdx.x / MAN_NCHUNK;
    const int c  = blockIdx.x % MAN_NCHUNK;
    const int t0 = c * MAN_TSUB;

    const float4* __restrict__ xb = x + (size_t)b * MAN_T * MAN_DV;

    // ---- cooperative load: rows [t0-50, t0+177], reflected at edges ----
    #pragma unroll 4
    for (int idx = threadIdx.x; idx < MAN_ROWS * MAN_DV; idx += MAN_NTH) {
        const int r   = idx / MAN_DV;
        const int dvv = idx % MAN_DV;
        int g = t0 - MAN_H + r;
        g = (g < 0) ? -g : g;
        g = (g >= MAN_T) ? (2 * MAN_T - 2 - g) : g;
        tile[idx] = __ldg(xb + (size_t)g * MAN_DV + dvv);
    }
    __syncthreads();

    // ---- compute: 20 dv-lanes x 16 segments of 8 outputs ----
    const int dv = threadIdx.x % MAN_DV;
    const int ts = (threadIdx.x / MAN_DV) * MAN_SEG;   // local output row start

    const float inv_k  = 1.0f / MAN_K;
    const float inv_k1 = 1.0f / (MAN_K - 1);

    float4 s1 = make_float4(0.f, 0.f, 0.f, 0.f);
    float4 s2 = make_float4(0.f, 0.f, 0.f, 0.f);

    // window for local output ts: tile rows [ts, ts+99]
    #pragma unroll 10
    for (int i = 0; i < MAN_K; ++i) {
        acc(s1, s2, tile[(ts + i) * MAN_DV + dv]);
    }

    float4* __restrict__ ob = out + ((size_t)b * MAN_T + t0) * MAN_DV + dv;

    #pragma unroll
    for (int j = 0; j < MAN_SEG; ++j) {
        const int t = ts + j;                      // local output row
        float4 xc = tile[(t + MAN_H) * MAN_DV + dv];
        float4 r;
        r.x = norm1(xc.x, s1.x, s2.x, inv_k, inv_k1);
        r.y = norm1(xc.y, s1.y, s2.y, inv_k, inv_k1);
        r.z = norm1(xc.z, s1.z, s2.z, inv_k, inv_k1);
        r.w = norm1(xc.w, s1.w, s2.w, inv_k, inv_k1);
        __stcs(ob + (size_t)t * MAN_DV, r);
        float4 va = tile[(t + MAN_K) * MAN_DV + dv];
        float4 vr = tile[t * MAN_DV + dv];
        step(s1, s2, va, vr);
    }
}

extern "C" void kernel_launch(void* const* d_in, const int* in_sizes, int n_in,
                              void* d_out, int out_size)
{
    const float4* x = (const float4*)d_in[0];
    float4* out = (float4*)d_out;
    (void)in_sizes; (void)n_in; (void)out_size;

    static bool attr_done = false;
    if (!attr_done) {
        cudaFuncSetAttribute(moving_avg_norm_v4,
                             cudaFuncAttributeMaxDynamicSharedMemorySize,
                             MAN_SMEM);
        attr_done = true;
    }

    const int grid = MAN_B * MAN_NCHUNK;   // 4096 blocks
    moving_avg_norm_v4<<<grid, MAN_NTH, MAN_SMEM>>>(x, out);
}

// round 5
// speedup vs baseline: 2.0308x; 1.0690x over previous
#include <cuda_runtime.h>

// MovingAvgNorm: x (B=32, T=16384, D=80) fp32, window K=100 over T,
// reflect pad (50 left, 49 right), unbiased std.
//
// R5: R4 smem tile + two-level window init. After loading the 228-row tile,
// the block computes 8-row group sums (27 groups x 20 dv). Each thread's
// window init becomes 12 group sums + 4 remainder rows (28 LDS) instead of
// 100 LDS — cutting block smem reads ~45% (R4 was crossbar-bound at 91% L1).

#define MAN_B      32
#define MAN_T      16384
#define MAN_DV     20          // 80 floats = 20 float4
#define MAN_K      100
#define MAN_H      50
#define MAN_TSUB   128
#define MAN_ROWS   (MAN_TSUB + MAN_K)     // 228
#define MAN_NTH    320
#define MAN_SEG    8
#define MAN_NCHUNK (MAN_T / MAN_TSUB)     // 128
#define MAN_G      8                       // group size (rows)
#define MAN_NGRP   27                      // groups needed: rows 0..215
#define MAN_TILE_F4 (MAN_ROWS * MAN_DV)            // 4560
#define MAN_GSUM_F4 (MAN_NGRP * MAN_DV)            // 540
#define MAN_SMEM   ((MAN_TILE_F4 + 2 * MAN_GSUM_F4) * 16)   // 90240 B

__device__ __forceinline__ void acc(float4& s1, float4& s2, float4 v) {
    s1.x += v.x; s1.y += v.y; s1.z += v.z; s1.w += v.w;
    s2.x = fmaf(v.x, v.x, s2.x);
    s2.y = fmaf(v.y, v.y, s2.y);
    s2.z = fmaf(v.z, v.z, s2.z);
    s2.w = fmaf(v.w, v.w, s2.w);
}

__device__ __forceinline__ void add4(float4& a, float4 b) {
    a.x += b.x; a.y += b.y; a.z += b.z; a.w += b.w;
}

__device__ __forceinline__ float norm1(float xc, float s1, float s2,
                                       float inv_k, float inv_k1) {
    float m   = s1 * inv_k;
    float var = (s2 - s1 * m) * inv_k1;
    float rsd = rsqrtf(fmaxf(var, 1e-24f));
    return (xc - m) * rsd;
}

__device__ __forceinline__ void step(float4& s1, float4& s2,
                                     float4 va, float4 vr) {
    s1.x += va.x - vr.x;  s1.y += va.y - vr.y;
    s1.z += va.z - vr.z;  s1.w += va.w - vr.w;
    s2.x = fmaf(va.x, va.x, fmaf(-vr.x, vr.x, s2.x));
    s2.y = fmaf(va.y, va.y, fmaf(-vr.y, vr.y, s2.y));
    s2.z = fmaf(va.z, va.z, fmaf(-vr.z, vr.z, s2.z));
    s2.w = fmaf(va.w, va.w, fmaf(-vr.w, vr.w, s2.w));
}

__global__ __launch_bounds__(MAN_NTH, 2) void moving_avg_norm_v5(
    const float4* __restrict__ x, float4* __restrict__ out)
{
    extern __shared__ float4 smem[];
    float4* tile  = smem;                                // [228*20]
    float4* gsum1 = smem + MAN_TILE_F4;                  // [27*20]
    float4* gsum2 = smem + MAN_TILE_F4 + MAN_GSUM_F4;    // [27*20]

    const int b  = blockIdx.x / MAN_NCHUNK;
    const int c  = blockIdx.x % MAN_NCHUNK;
    const int t0 = c * MAN_TSUB;

    const float4* __restrict__ xb = x + (size_t)b * MAN_T * MAN_DV;

    // ---- cooperative load: rows [t0-50, t0+177], reflected at edges ----
    #pragma unroll 4
    for (int idx = threadIdx.x; idx < MAN_TILE_F4; idx += MAN_NTH) {
        const int r   = idx / MAN_DV;
        const int dvv = idx % MAN_DV;
        int g = t0 - MAN_H + r;
        g = (g < 0) ? -g : g;
        g = (g >= MAN_T) ? (2 * MAN_T - 2 - g) : g;
        tile[idx] = __ldg(xb + (size_t)g * MAN_DV + dvv);
    }
    __syncthreads();

    // ---- 8-row group partial sums: 27 groups x 20 dv = 540 entries ----
    #pragma unroll
    for (int idx = threadIdx.x; idx < MAN_GSUM_F4; idx += MAN_NTH) {
        const int g   = idx / MAN_DV;
        const int dvv = idx % MAN_DV;
        float4 p1 = make_float4(0.f, 0.f, 0.f, 0.f);
        float4 p2 = make_float4(0.f, 0.f, 0.f, 0.f);
        const float4* rp = tile + (size_t)(g * MAN_G) * MAN_DV + dvv;
        #pragma unroll
        for (int i = 0; i < MAN_G; ++i)
            acc(p1, p2, rp[i * MAN_DV]);
        gsum1[idx] = p1;
        gsum2[idx] = p2;
    }
    __syncthreads();

    // ---- compute: 20 dv-lanes x 16 segments of 8 outputs ----
    const int dv  = threadIdx.x % MAN_DV;
    const int seg = threadIdx.x / MAN_DV;     // 0..15
    const int ts  = seg * MAN_SEG;            // local output row start

    const float inv_k  = 1.0f / MAN_K;
    const float inv_k1 = 1.0f / (MAN_K - 1);

    // window [ts, ts+100) = groups seg..seg+11 (96 rows) + rows ts+96..ts+99
    float4 s1 = make_float4(0.f, 0.f, 0.f, 0.f);
    float4 s2 = make_float4(0.f, 0.f, 0.f, 0.f);
    #pragma unroll
    for (int j = 0; j < 12; ++j) {
        add4(s1, gsum1[(seg + j) * MAN_DV + dv]);
        add4(s2, gsum2[(seg + j) * MAN_DV + dv]);
    }
    #pragma unroll
    for (int i = 0; i < 4; ++i)
        acc(s1, s2, tile[(ts + 96 + i) * MAN_DV + dv]);

    float4* __restrict__ ob = out + ((size_t)b * MAN_T + t0) * MAN_DV + dv;

    #pragma unroll
    for (int j = 0; j < MAN_SEG; ++j) {
        const int t = ts + j;                      // local output row
        float4 xc = tile[(t + MAN_H) * MAN_DV + dv];
        float4 r;
        r.x = norm1(xc.x, s1.x, s2.x, inv_k, inv_k1);
        r.y = norm1(xc.y, s1.y, s2.y, inv_k, inv_k1);
        r.z = norm1(xc.z, s1.z, s2.z, inv_k, inv_k1);
        r.w = norm1(xc.w, s1.w, s2.w, inv_k, inv_k1);
        __stcs(ob + (size_t)t * MAN_DV, r);
        float4 va = tile[(t + MAN_K) * MAN_DV + dv];
        float4 vr = tile[t * MAN_DV + dv];
        step(s1, s2, va, vr);
    }
}

extern "C" void kernel_launch(void* const* d_in, const int* in_sizes, int n_in,
                              void* d_out, int out_size)
{
    const float4* x = (const float4*)d_in[0];
    float4* out = (float4*)d_out;
    (void)in_sizes; (void)n_in; (void)out_size;

    static bool attr_done = false;
    if (!attr_done) {
        cudaFuncSetAttribute(moving_avg_norm_v5,
                             cudaFuncAttributeMaxDynamicSharedMemorySize,
                             MAN_SMEM);
        attr_done = true;
    }

    const int grid = MAN_B * MAN_NCHUNK;   // 4096 blocks
    moving_avg_norm_v5<<<grid, MAN_NTH, MAN_SMEM>>>(x, out);
}

// round 6
// speedup vs baseline: 2.7544x; 1.3563x over previous
#include <cuda_runtime.h>

// MovingAvgNorm: x (B=32, T=16384, D=80) fp32, window K=100 over T,
// reflect pad (50 left, 49 right), unbiased std.
//
// R6: drop the smem row tile (it capped occupancy at 2 blocks/SM). Keep only
// the 8-row group sums in smem (17.3 KB). All row reads go through LDG/L1/L2
// (R3 showed the cache handles them). One barrier phase instead of two,
// __launch_bounds__(320,4) -> 40 warps/SM for latency hiding.

#define MAN_B      32
#define MAN_T      16384
#define MAN_DV     20          // 80 floats = 20 float4
#define MAN_K      100
#define MAN_H      50
#define MAN_TSUB   128
#define MAN_NTH    320
#define MAN_SEG    8
#define MAN_NCHUNK (MAN_T / MAN_TSUB)     // 128
#define MAN_G      8
#define MAN_NGRP   27                      // groups cover local rows 0..215
#define MAN_GSUM_F4 (MAN_NGRP * MAN_DV)    // 540
#define MAN_SMEM   (2 * MAN_GSUM_F4 * 16)  // 17280 B

__device__ __forceinline__ int refl(int o) {
    if (o < 0) return -o;
    if (o >= MAN_T) return 2 * MAN_T - 2 - o;
    return o;
}

__device__ __forceinline__ void acc(float4& s1, float4& s2, float4 v) {
    s1.x += v.x; s1.y += v.y; s1.z += v.z; s1.w += v.w;
    s2.x = fmaf(v.x, v.x, s2.x);
    s2.y = fmaf(v.y, v.y, s2.y);
    s2.z = fmaf(v.z, v.z, s2.z);
    s2.w = fmaf(v.w, v.w, s2.w);
}

__device__ __forceinline__ void add4(float4& a, float4 b) {
    a.x += b.x; a.y += b.y; a.z += b.z; a.w += b.w;
}

__device__ __forceinline__ float norm1(float xc, float s1, float s2,
                                       float inv_k, float inv_k1) {
    float m   = s1 * inv_k;
    float var = (s2 - s1 * m) * inv_k1;
    float rsd = rsqrtf(fmaxf(var, 1e-24f));
    return (xc - m) * rsd;
}

__device__ __forceinline__ void step(float4& s1, float4& s2,
                                     float4 va, float4 vr) {
    s1.x += va.x - vr.x;  s1.y += va.y - vr.y;
    s1.z += va.z - vr.z;  s1.w += va.w - vr.w;
    s2.x = fmaf(va.x, va.x, fmaf(-vr.x, vr.x, s2.x));
    s2.y = fmaf(va.y, va.y, fmaf(-vr.y, vr.y, s2.y));
    s2.z = fmaf(va.z, va.z, fmaf(-vr.z, vr.z, s2.z));
    s2.w = fmaf(va.w, va.w, fmaf(-vr.w, vr.w, s2.w));
}

__global__ __launch_bounds__(MAN_NTH, 4) void moving_avg_norm_v6(
    const float4* __restrict__ x, float4* __restrict__ out)
{
    extern __shared__ float4 smem[];
    float4* gsum1 = smem;                  // [27*20]
    float4* gsum2 = smem + MAN_GSUM_F4;    // [27*20]

    const int b  = blockIdx.x / MAN_NCHUNK;
    const int c  = blockIdx.x % MAN_NCHUNK;
    const int t0 = c * MAN_TSUB;

    const float4* __restrict__ xb = x + (size_t)b * MAN_T * MAN_DV;

    const bool edge = (c == 0) || (c == MAN_NCHUNK - 1);

    // ---- group partial sums over global rows [t0-50+8g, +8), 27 groups ----
    if (!edge) {
        #pragma unroll 2
        for (int idx = threadIdx.x; idx < MAN_GSUM_F4; idx += MAN_NTH) {
            const int g   = idx / MAN_DV;
            const int dvv = idx % MAN_DV;
            const float4* rp = xb + (size_t)(t0 - MAN_H + g * MAN_G) * MAN_DV + dvv;
            float4 p1 = make_float4(0.f, 0.f, 0.f, 0.f);
            float4 p2 = make_float4(0.f, 0.f, 0.f, 0.f);
            #pragma unroll
            for (int i = 0; i < MAN_G; ++i)
                acc(p1, p2, __ldg(rp + i * MAN_DV));
            gsum1[idx] = p1;
            gsum2[idx] = p2;
        }
    } else {
        #pragma unroll 2
        for (int idx = threadIdx.x; idx < MAN_GSUM_F4; idx += MAN_NTH) {
            const int g   = idx / MAN_DV;
            const int dvv = idx % MAN_DV;
            const int r0  = t0 - MAN_H + g * MAN_G;
            float4 p1 = make_float4(0.f, 0.f, 0.f, 0.f);
            float4 p2 = make_float4(0.f, 0.f, 0.f, 0.f);
            #pragma unroll
            for (int i = 0; i < MAN_G; ++i)
                acc(p1, p2, __ldg(xb + (size_t)refl(r0 + i) * MAN_DV + dvv));
            gsum1[idx] = p1;
            gsum2[idx] = p2;
        }
    }
    __syncthreads();

    // ---- compute: 20 dv-lanes x 16 segments of 8 outputs ----
    const int dv  = threadIdx.x % MAN_DV;
    const int seg = threadIdx.x / MAN_DV;     // 0..15
    const int ts  = seg * MAN_SEG;            // local output row start

    const float inv_k  = 1.0f / MAN_K;
    const float inv_k1 = 1.0f / (MAN_K - 1);

    // window for output ts: local rows [ts, ts+100) relative to t0-50
    //   = groups seg..seg+11 (96 rows) + global rows t0+ts+46 .. +49
    float4 s1 = make_float4(0.f, 0.f, 0.f, 0.f);
    float4 s2 = make_float4(0.f, 0.f, 0.f, 0.f);
    #pragma unroll
    for (int j = 0; j < 12; ++j) {
        add4(s1, gsum1[(seg + j) * MAN_DV + dv]);
        add4(s2, gsum2[(seg + j) * MAN_DV + dv]);
    }

    float4* __restrict__ ob = out + ((size_t)b * MAN_T + t0) * MAN_DV + dv;

    if (!edge) {
        const float4* rp = xb + (size_t)(t0 + ts) * MAN_DV + dv;
        #pragma unroll
        for (int i = 0; i < 4; ++i)
            acc(s1, s2, __ldg(rp + (size_t)(46 + i) * MAN_DV));
        #pragma unroll
        for (int j = 0; j < MAN_SEG; ++j) {
            float4 xc = __ldg(rp + (size_t)j * MAN_DV);
            float4 va = __ldg(rp + (size_t)(j + MAN_H) * MAN_DV);
            float4 vr = __ldg(rp + (size_t)(j - MAN_H) * MAN_DV);
            float4 r;
            r.x = norm1(xc.x, s1.x, s2.x, inv_k, inv_k1);
            r.y = norm1(xc.y, s1.y, s2.y, inv_k, inv_k1);
            r.z = norm1(xc.z, s1.z, s2.z, inv_k, inv_k1);
            r.w = norm1(xc.w, s1.w, s2.w, inv_k, inv_k1);
            __stcs(ob + (size_t)(ts + j) * MAN_DV, r);
            step(s1, s2, va, vr);
        }
    } else {
        const int tg = t0 + ts;
        #pragma unroll
        for (int i = 0; i < 4; ++i)
            acc(s1, s2, __ldg(xb + (size_t)refl(tg + 46 + i) * MAN_DV + dv));
        #pragma unroll
        for (int j = 0; j < MAN_SEG; ++j) {
            float4 xc = __ldg(xb + (size_t)(tg + j) * MAN_DV + dv);
            float4 va = __ldg(xb + (size_t)refl(tg + j + MAN_H) * MAN_DV + dv);
            float4 vr = __ldg(xb + (size_t)refl(tg + j - MAN_H) * MAN_DV + dv);
            float4 r;
            r.x = norm1(xc.x, s1.x, s2.x, inv_k, inv_k1);
            r.y = norm1(xc.y, s1.y, s2.y, inv_k, inv_k1);
            r.z = norm1(xc.z, s1.z, s2.z, inv_k, inv_k1);
            r.w = norm1(xc.w, s1.w, s2.w, inv_k, inv_k1);
            __stcs(ob + (size_t)(ts + j) * MAN_DV, r);
            step(s1, s2, va, vr);
        }
    }
}

extern "C" void kernel_launch(void* const* d_in, const int* in_sizes, int n_in,
                              void* d_out, int out_size)
{
    const float4* x = (const float4*)d_in[0];
    float4* out = (float4*)d_out;
    (void)in_sizes; (void)n_in; (void)out_size;

    const int grid = MAN_B * MAN_NCHUNK;   // 4096 blocks
    moving_avg_norm_v6<<<grid, MAN_NTH, MAN_SMEM>>>(x, out);
}

// round 7
// speedup vs baseline: 2.7989x; 1.0162x over previous
#include <cuda_runtime.h>

// MovingAvgNorm: x (B=32, T=16384, D=80) fp32, window K=100 over T,
// reflect pad (50 left, 49 right), unbiased std.
//
// R7: TSUB=256/SEG=16 (amortize fixed costs over 2x outputs per thread) +
// exclusive prefix scan over the 8-row group sums so window init is 4 LDS
// (gpre[2s+12]-gpre[2s]) instead of 24. l1tex traffic ~1.6GB -> ~1.14GB;
// smem 27.5KB -> 4 blocks/SM.

#define MAN_B      32
#define MAN_T      16384
#define MAN_DV     20          // 80 floats = 20 float4
#define MAN_K      100
#define MAN_H      50
#define MAN_TSUB   256
#define MAN_NTH    320
#define MAN_SEG    16
#define MAN_NCHUNK (MAN_T / MAN_TSUB)     // 64
#define MAN_G      8
#define MAN_NGRP   42                      // groups cover local rows 0..335
#define MAN_GPRE   (MAN_NGRP + 1)          // 43 (exclusive prefix, +end)
#define MAN_GARR   (MAN_GPRE * MAN_DV)     // 860 float4 per array
#define MAN_SMEM   (2 * MAN_GARR * 16)     // 27520 B

__device__ __forceinline__ int refl(int o) {
    if (o < 0) return -o;
    if (o >= MAN_T) return 2 * MAN_T - 2 - o;
    return o;
}

__device__ __forceinline__ void acc(float4& s1, float4& s2, float4 v) {
    s1.x += v.x; s1.y += v.y; s1.z += v.z; s1.w += v.w;
    s2.x = fmaf(v.x, v.x, s2.x);
    s2.y = fmaf(v.y, v.y, s2.y);
    s2.z = fmaf(v.z, v.z, s2.z);
    s2.w = fmaf(v.w, v.w, s2.w);
}

__device__ __forceinline__ float norm1(float xc, float s1, float s2,
                                       float inv_k, float inv_k1) {
    float m   = s1 * inv_k;
    float var = (s2 - s1 * m) * inv_k1;
    float rsd = rsqrtf(fmaxf(var, 1e-24f));
    return (xc - m) * rsd;
}

__device__ __forceinline__ void step(float4& s1, float4& s2,
                                     float4 va, float4 vr) {
    s1.x += va.x - vr.x;  s1.y += va.y - vr.y;
    s1.z += va.z - vr.z;  s1.w += va.w - vr.w;
    s2.x = fmaf(va.x, va.x, fmaf(-vr.x, vr.x, s2.x));
    s2.y = fmaf(va.y, va.y, fmaf(-vr.y, vr.y, s2.y));
    s2.z = fmaf(va.z, va.z, fmaf(-vr.z, vr.z, s2.z));
    s2.w = fmaf(va.w, va.w, fmaf(-vr.w, vr.w, s2.w));
}

__global__ __launch_bounds__(MAN_NTH, 4) void moving_avg_norm_v7(
    const float4* __restrict__ x, float4* __restrict__ out)
{
    extern __shared__ float4 smem[];
    float4* g1 = smem;              // [43*20] group sums -> exclusive prefix
    float4* g2 = smem + MAN_GARR;   // [43*20]

    const int b  = blockIdx.x / MAN_NCHUNK;
    const int c  = blockIdx.x % MAN_NCHUNK;
    const int t0 = c * MAN_TSUB;

    const float4* __restrict__ xb = x + (size_t)b * MAN_T * MAN_DV;
    const bool edge = (c == 0) || (c == MAN_NCHUNK - 1);

    // ---- phase 1: 8-row group sums, groups 0..41 over local rows 0..335
    //      (local row L = global t0 - 50 + L) ----
    if (!edge) {
        #pragma unroll 3
        for (int idx = threadIdx.x; idx < MAN_NGRP * MAN_DV; idx += MAN_NTH) {
            const int g   = idx / MAN_DV;
            const int dvv = idx % MAN_DV;
            const float4* rp = xb + (size_t)(t0 - MAN_H + g * MAN_G) * MAN_DV + dvv;
            float4 p1 = make_float4(0.f, 0.f, 0.f, 0.f);
            float4 p2 = make_float4(0.f, 0.f, 0.f, 0.f);
            #pragma unroll
            for (int i = 0; i < MAN_G; ++i)
                acc(p1, p2, __ldg(rp + i * MAN_DV));
            g1[idx] = p1;
            g2[idx] = p2;
        }
    } else {
        #pragma unroll 3
        for (int idx = threadIdx.x; idx < MAN_NGRP * MAN_DV; idx += MAN_NTH) {
            const int g   = idx / MAN_DV;
            const int dvv = idx % MAN_DV;
            const int r0  = t0 - MAN_H + g * MAN_G;
            float4 p1 = make_float4(0.f, 0.f, 0.f, 0.f);
            float4 p2 = make_float4(0.f, 0.f, 0.f, 0.f);
            #pragma unroll
            for (int i = 0; i < MAN_G; ++i)
                acc(p1, p2, __ldg(xb + (size_t)refl(r0 + i) * MAN_DV + dvv));
            g1[idx] = p1;
            g2[idx] = p2;
        }
    }
    __syncthreads();

    // ---- phase 2: in-place exclusive prefix scan over groups (40 lanes:
    //      tid/20 selects array, tid%20 selects dv) ----
    if (threadIdx.x < 2 * MAN_DV) {
        float4* A = (threadIdx.x < MAN_DV) ? g1 : g2;
        const int dvv = threadIdx.x % MAN_DV;
        float4 run = make_float4(0.f, 0.f, 0.f, 0.f);
        #pragma unroll 6
        for (int g = 0; g < MAN_NGRP; ++g) {
            float4 tmp = A[g * MAN_DV + dvv];
            A[g * MAN_DV + dvv] = run;
            run.x += tmp.x; run.y += tmp.y; run.z += tmp.z; run.w += tmp.w;
        }
        A[MAN_NGRP * MAN_DV + dvv] = run;
    }
    __syncthreads();

    // ---- phase 3: 20 dv-lanes x 16 segments of 16 outputs ----
    const int dv  = threadIdx.x % MAN_DV;
    const int seg = threadIdx.x / MAN_DV;      // 0..15
    const int ts  = seg * MAN_SEG;             // local output row start (mult of 16)

    const float inv_k  = 1.0f / MAN_K;
    const float inv_k1 = 1.0f / (MAN_K - 1);

    // window for output ts: local rows [ts, ts+100) = groups 2s..2s+11 (96)
    //   + global rows t0+ts+46 .. +49
    float4 s1, s2;
    {
        float4 lo1 = g1[(2 * seg) * MAN_DV + dv];
        float4 hi1 = g1[(2 * seg + 12) * MAN_DV + dv];
        float4 lo2 = g2[(2 * seg) * MAN_DV + dv];
        float4 hi2 = g2[(2 * seg + 12) * MAN_DV + dv];
        s1 = make_float4(hi1.x - lo1.x, hi1.y - lo1.y, hi1.z - lo1.z, hi1.w - lo1.w);
        s2 = make_float4(hi2.x - lo2.x, hi2.y - lo2.y, hi2.z - lo2.z, hi2.w - lo2.w);
    }

    float4* __restrict__ ob = out + ((size_t)b * MAN_T + t0) * MAN_DV + dv;

    if (!edge) {
        const float4* rp = xb + (size_t)(t0 + ts) * MAN_DV + dv;
        #pragma unroll
        for (int i = 0; i < 4; ++i)
            acc(s1, s2, __ldg(rp + (size_t)(46 + i) * MAN_DV));
        #pragma unroll 8
        for (int j = 0; j < MAN_SEG; ++j) {
            float4 xc = __ldg(rp + (size_t)j * MAN_DV);
            float4 va = __ldg(rp + (size_t)(j + MAN_H) * MAN_DV);
            float4 vr = __ldg(rp + (size_t)(j - MAN_H) * MAN_DV);
            float4 r;
            r.x = norm1(xc.x, s1.x, s2.x, inv_k, inv_k1);
            r.y = norm1(xc.y, s1.y, s2.y, inv_k, inv_k1);
            r.z = norm1(xc.z, s1.z, s2.z, inv_k, inv_k1);
            r.w = norm1(xc.w, s1.w, s2.w, inv_k, inv_k1);
            __stcs(ob + (size_t)(ts + j) * MAN_DV, r);
            step(s1, s2, va, vr);
        }
    } else {
        const int tg = t0 + ts;
        #pragma unroll
        for (int i = 0; i < 4; ++i)
            acc(s1, s2, __ldg(xb + (size_t)refl(tg + 46 + i) * MAN_DV + dv));
        #pragma unroll 4
        for (int j = 0; j < MAN_SEG; ++j) {
            float4 xc = __ldg(xb + (size_t)(tg + j) * MAN_DV + dv);
            float4 va = __ldg(xb + (size_t)refl(tg + j + MAN_H) * MAN_DV + dv);
            float4 vr = __ldg(xb + (size_t)refl(tg + j - MAN_H) * MAN_DV + dv);
            float4 r;
            r.x = norm1(xc.x, s1.x, s2.x, inv_k, inv_k1);
            r.y = norm1(xc.y, s1.y, s2.y, inv_k, inv_k1);
            r.z = norm1(xc.z, s1.z, s2.z, inv_k, inv_k1);
            r.w = norm1(xc.w, s1.w, s2.w, inv_k, inv_k1);
            __stcs(ob + (size_t)(ts + j) * MAN_DV, r);
            step(s1, s2, va, vr);
        }
    }
}

extern "C" void kernel_launch(void* const* d_in, const int* in_sizes, int n_in,
                              void* d_out, int out_size)
{
    const float4* x = (const float4*)d_in[0];
    float4* out = (float4*)d_out;
    (void)in_sizes; (void)n_in; (void)out_size;

    const int grid = MAN_B * MAN_NCHUNK;   // 2048 blocks
    moving_avg_norm_v7<<<grid, MAN_NTH, MAN_SMEM>>>(x, out);
}